// round 2
// baseline (speedup 1.0000x reference)
#include <cuda_runtime.h>
#include <math.h>

#define NMAX 100000
#define C    64
#define HID  16
#define KNN  16
#define FULL 0xFFFFFFFFu

// Scratch (device globals: no allocation allowed in kernel_launch)
__device__ float g_outse[(size_t)NMAX * C];   // stage-1 output (gated features)
__device__ float g_rowstat[(size_t)NMAX * 2]; // per-point (rowsum, rowmax) of outse
__device__ float g_z[(size_t)NMAX * 2];       // stage-2 (mean, max) pooled stats

// ---------------------------------------------------------------------------
// Kernel 1: channel attention. PERSISTENT warp-per-point loop.
//   Weights live in registers (loaded once per thread, amortized over ~42
//   points per warp) -> zero shared-memory traffic per point.
//   idx row loaded as 4 uniform LDG.128.
// ---------------------------------------------------------------------------
__global__ __launch_bounds__(256) void k1_gate(
    const float* __restrict__ xF,
    const float* __restrict__ W1,   // (C, HID)
    const float* __restrict__ b1,   // (HID,)
    const float* __restrict__ W2,   // (HID, C)
    const float* __restrict__ b2,   // (C,)
    const int*   __restrict__ idx,  // (N, KNN)
    int N)
{
    const int lane  = threadIdx.x & 31;
    const int wpb   = blockDim.x >> 5;
    const int gwarp = blockIdx.x * wpb + (threadIdx.x >> 5);
    const int nwarp = gridDim.x * wpb;

    // ---- register-resident weights: lane owns channels 2l, 2l+1 ----
    // w1a[j] = W1[2l][j], w1b[j] = W1[2l+1][j]
    float w1a[HID], w1b[HID];
    {
        const float4* ra = (const float4*)(W1 + (size_t)(2 * lane) * HID);
        const float4* rb = (const float4*)(W1 + (size_t)(2 * lane + 1) * HID);
        #pragma unroll
        for (int q = 0; q < 4; q++) {
            float4 va = __ldg(ra + q);
            w1a[4*q+0] = va.x; w1a[4*q+1] = va.y; w1a[4*q+2] = va.z; w1a[4*q+3] = va.w;
            float4 vb = __ldg(rb + q);
            w1b[4*q+0] = vb.x; w1b[4*q+1] = vb.y; w1b[4*q+2] = vb.z; w1b[4*q+3] = vb.w;
        }
    }
    // w2r[j] = (W2[j][2l], W2[j][2l+1])
    float2 w2r[HID];
    #pragma unroll
    for (int j = 0; j < HID; j++)
        w2r[j] = __ldg((const float2*)(W2 + (size_t)j * C + 2 * lane));

    const float  bias1 = __ldg(b1 + (lane & 15));
    const float2 b2v   = __ldg((const float2*)(b2 + 2 * lane));

    for (int n = gwarp; n < N; n += nwarp) {
        // ---- 4 uniform LDG.128 for the 16 neighbor indices ----
        const int4* ib = (const int4*)(idx + (size_t)n * KNN);
        int4 q0 = __ldg(ib + 0), q1 = __ldg(ib + 1),
             q2 = __ldg(ib + 2), q3 = __ldg(ib + 3);
        const int nb[KNN] = { q0.x, q0.y, q0.z, q0.w,  q1.x, q1.y, q1.z, q1.w,
                              q2.x, q2.y, q2.z, q2.w,  q3.x, q3.y, q3.z, q3.w };

        // ---- gather + pool: 16 independent coalesced 256B row reads ----
        float m0 = 0.f, m1 = 0.f, x0 = -INFINITY, x1 = -INFINITY;
        #pragma unroll
        for (int k = 0; k < KNN; k++) {
            float2 v = __ldg((const float2*)(xF + (size_t)nb[k] * C + 2 * lane));
            m0 += v.x; m1 += v.y;
            x0 = fmaxf(x0, v.x); x1 = fmaxf(x1, v.y);
        }
        m0 *= (1.f / KNN); m1 *= (1.f / KNN);

        // ---- layer-1 partials from register weights ----
        float p[32];
        #pragma unroll
        for (int j = 0; j < HID; j++) {
            p[j]      = m0 * w1a[j] + m1 * w1b[j];
            p[j + 16] = x0 * w1a[j] + x1 * w1b[j];
        }

        // ---- vector-halving butterfly: 31 shfls reduce all 32 partials.
        //      After 5 rounds, lane l holds the full sum of element l. ----
        #pragma unroll
        for (int step = 0; step < 5; step++) {
            const int  off = 16 >> step;
            const int  nv  = 16 >> step;
            const bool up  = (lane & off) != 0;
            #pragma unroll
            for (int i = 0; i < nv; i++) {
                float send = up ? p[i] : p[i + nv];
                float recv = __shfl_xor_sync(FULL, send, off);
                float keep = up ? p[i + nv] : p[i];
                p[i] = keep + recv;
            }
        }

        // lane<16: mean-path hidden 'lane'; lane>=16: max-path hidden 'lane-16'
        float h  = fmaxf(p[0] + bias1, 0.f);
        float hs = h + __shfl_xor_sync(FULL, h, 16);   // hs[j] on lanes j and j+16

        // ---- layer 2 from register weights ----
        float a0 = 2.f * b2v.x, a1 = 2.f * b2v.y;
        #pragma unroll
        for (int j = 0; j < HID; j++) {
            float hj = __shfl_sync(FULL, hs, j);
            a0 += hj * w2r[j].x;
            a1 += hj * w2r[j].y;
        }

        float2 xv = __ldg((const float2*)(xF + (size_t)n * C + 2 * lane));
        float o0 = xv.x / (1.f + expf(-a0));
        float o1 = xv.y / (1.f + expf(-a1));
        *(float2*)(g_outse + (size_t)n * C + 2 * lane) = make_float2(o0, o1);

        // ---- rowsum/rowmax of outse for factored stage-2 pooling ----
        float s  = o0 + o1;
        float mx = fmaxf(o0, o1);
        #pragma unroll
        for (int off = 16; off >= 1; off >>= 1) {
            s  += __shfl_xor_sync(FULL, s, off);
            mx  = fmaxf(mx, __shfl_xor_sync(FULL, mx, off));
        }
        if (lane == 0)
            *(float2*)(g_rowstat + 2 * (size_t)n) = make_float2(s, mx);
    }
}

// ---------------------------------------------------------------------------
// Kernel 2: z = (mean over k*c, max over k*c) of outse[idx], factored through
//           per-point rowstats. thread-per-point, 16 x 8B gathers.
// ---------------------------------------------------------------------------
__global__ __launch_bounds__(256) void k2_z(const int* __restrict__ idx, int N)
{
    int n = blockIdx.x * blockDim.x + threadIdx.x;
    if (n >= N) return;
    const int4* ib = (const int4*)(idx + (size_t)n * KNN);
    int4 q0 = __ldg(ib + 0), q1 = __ldg(ib + 1),
         q2 = __ldg(ib + 2), q3 = __ldg(ib + 3);
    const int nb[KNN] = { q0.x, q0.y, q0.z, q0.w,  q1.x, q1.y, q1.z, q1.w,
                          q2.x, q2.y, q2.z, q2.w,  q3.x, q3.y, q3.z, q3.w };
    float s = 0.f, mx = -INFINITY;
    #pragma unroll
    for (int k = 0; k < KNN; k++) {
        float2 rs = __ldg((const float2*)(g_rowstat + 2 * (size_t)nb[k]));
        s += rs.x;
        mx = fmaxf(mx, rs.y);
    }
    *(float2*)(g_z + 2 * (size_t)n) = make_float2(s * (1.f / (KNN * C)), mx);
}

// ---------------------------------------------------------------------------
// Kernel 3: sparse conv3d(2->1) over 27 voxel neighbors + final gating.
//           warp-per-point: lanes 0..26 each handle one conv tap.
// ---------------------------------------------------------------------------
__global__ __launch_bounds__(256) void k3_out(
    const float* __restrict__ conv_w,   // (27, 2, 1)
    const int*   __restrict__ conv_idx, // (N, 27)
    float*       __restrict__ out,
    int N)
{
    const int n    = (blockIdx.x * blockDim.x + threadIdx.x) >> 5;
    const int lane = threadIdx.x & 31;
    if (n >= N) return;

    float f = 0.f;
    if (lane < 27) {
        int m = __ldg(conv_idx + (size_t)n * 27 + lane);
        if (m >= 0) {
            float2 zz = __ldg((const float2*)(g_z + 2 * (size_t)m));
            float2 cw = __ldg((const float2*)(conv_w + 2 * lane));
            f = zz.x * cw.x + zz.y * cw.y;
        }
    }
    #pragma unroll
    for (int off = 16; off >= 1; off >>= 1)
        f += __shfl_xor_sync(FULL, f, off);

    float sg = 1.f / (1.f + expf(-f));
    float2 o = *(const float2*)(g_outse + (size_t)n * C + 2 * lane);
    *(float2*)(out + (size_t)n * C + 2 * lane) = make_float2(o.x * sg, o.y * sg);
}

// ---------------------------------------------------------------------------
// Launch: inputs in metadata order:
//   0 x_F (N*C f32), 1 W1 (C*HID), 2 b1 (HID), 3 W2 (HID*C), 4 b2 (C),
//   5 conv_w (27*2), 6 idx (N*KNN i32), 7 conv_idx (N*27 i32)
// ---------------------------------------------------------------------------
extern "C" void kernel_launch(void* const* d_in, const int* in_sizes, int n_in,
                              void* d_out, int out_size)
{
    const float* xF  = (const float*)d_in[0];
    const float* W1  = (const float*)d_in[1];
    const float* b1  = (const float*)d_in[2];
    const float* W2  = (const float*)d_in[3];
    const float* b2  = (const float*)d_in[4];
    const float* cw  = (const float*)d_in[5];
    const int*   idx = (const int*)d_in[6];
    const int*   cid = (const int*)d_in[7];
    float*       out = (float*)d_out;

    const int N = in_sizes[0] / C;                 // 100000

    k1_gate<<<304, 256>>>(xF, W1, b1, W2, b2, idx, N);   // persistent warps
    k2_z  <<<(N + 255) / 256, 256>>>(idx, N);
    k3_out<<<(N * 32 + 255) / 256, 256>>>(cw, cid, out, N);
}

// round 3
// speedup vs baseline: 1.6441x; 1.6441x over previous
#include <cuda_runtime.h>
#include <math.h>

#define NMAX 100000
#define C    64
#define HID  16
#define KNN  16
#define FULL 0xFFFFFFFFu

// Scratch (device globals: no allocation allowed in kernel_launch)
__device__ float g_outse[(size_t)NMAX * C];   // stage-1 output (gated features)
__device__ float g_rowstat[(size_t)NMAX * 2]; // per-point (rowsum, rowmax) of outse
__device__ float g_z[(size_t)NMAX * 2];       // stage-2 (mean, max) pooled stats

// ---------------------------------------------------------------------------
// Kernel 1: channel attention. HALF-WARP per point (2 points per warp).
//   Lane layout: half = lane>>4, hl = lane&15. Point n = 2*warp + half.
//   Lane hl owns channels 4hl..4hl+3 (all accesses float4).
//   Both halves read identical smem weight addresses -> broadcast-merged.
// ---------------------------------------------------------------------------
__global__ __launch_bounds__(256) void k1_gate(
    const float* __restrict__ xF,
    const float* __restrict__ W1,   // (C, HID)
    const float* __restrict__ b1,   // (HID,)
    const float* __restrict__ W2,   // (HID, C)
    const float* __restrict__ b2,   // (C,)
    const int*   __restrict__ idx,  // (N, KNN)
    int N)
{
    // sW1p[j*16+hl] = (W1[4hl+0][j], W1[4hl+1][j], W1[4hl+2][j], W1[4hl+3][j])
    // sW2p[j*16+hl] = (W2[j][4hl+0], ..., W2[j][4hl+3])  == ((float4*)W2)[j*16+hl]
    __shared__ float4 sW1p[HID * 16];
    __shared__ float4 sW2p[HID * 16];

    const int tid = threadIdx.x;
    for (int i = tid; i < HID * 16; i += blockDim.x) {
        int j = i >> 4, h = i & 15;
        sW1p[i] = make_float4(W1[(4*h+0)*HID + j], W1[(4*h+1)*HID + j],
                              W1[(4*h+2)*HID + j], W1[(4*h+3)*HID + j]);
        sW2p[i] = __ldg((const float4*)W2 + i);
    }
    __syncthreads();

    const int lane = tid & 31;
    const int half = lane >> 4;
    const int hl   = lane & 15;
    const int warp = blockIdx.x * (blockDim.x >> 5) + (tid >> 5);
    const int n    = 2 * warp + half;
    if (n >= N) return;

    const float  b1v = __ldg(b1 + hl);
    const float4 b2v = __ldg((const float4*)(b2 + 4 * hl));

    // ---- neighbor indices: 4 uniform-per-half LDG.128 ----
    const int4* ib = (const int4*)(idx + (size_t)n * KNN);
    int4 q0 = __ldg(ib + 0), q1 = __ldg(ib + 1),
         q2 = __ldg(ib + 2), q3 = __ldg(ib + 3);
    const int nb[KNN] = { q0.x, q0.y, q0.z, q0.w,  q1.x, q1.y, q1.z, q1.w,
                          q2.x, q2.y, q2.z, q2.w,  q3.x, q3.y, q3.z, q3.w };

    // ---- gather + pool: 16 rows x 256B, each inst covers both points ----
    float4 m  = make_float4(0.f, 0.f, 0.f, 0.f);
    float4 mx = make_float4(-INFINITY, -INFINITY, -INFINITY, -INFINITY);
    #pragma unroll
    for (int k = 0; k < KNN; k++) {
        float4 v = __ldg((const float4*)(xF + (size_t)nb[k] * C + 4 * hl));
        m.x += v.x; m.y += v.y; m.z += v.z; m.w += v.w;
        mx.x = fmaxf(mx.x, v.x); mx.y = fmaxf(mx.y, v.y);
        mx.z = fmaxf(mx.z, v.z); mx.w = fmaxf(mx.w, v.w);
    }
    const float inv = 1.f / KNN;
    m.x *= inv; m.y *= inv; m.z *= inv; m.w *= inv;

    // ---- layer-1 partials: p[2j]=mean-path unit j, p[2j+1]=max-path unit j ----
    float p[32];
    #pragma unroll
    for (int j = 0; j < HID; j++) {
        float4 w = sW1p[j * 16 + hl];
        p[2*j]   = m.x*w.x  + m.y*w.y  + m.z*w.z  + m.w*w.w;
        p[2*j+1] = mx.x*w.x + mx.y*w.y + mx.z*w.z + mx.w*w.w;
    }

    // ---- 16-lane vector-halving butterfly: 4 steps, 30 shfls for 32 values.
    //      Final: lane hl holds p[0]=elem 2hl (mean_hl), p[1]=elem 2hl+1 (max_hl).
    #pragma unroll
    for (int step = 0; step < 4; step++) {
        const int  off = 8 >> step;     // 8,4,2,1 (stays within half)
        const int  nv  = 16 >> step;    // 16,8,4,2
        const bool up  = (hl & off) != 0;
        #pragma unroll
        for (int i = 0; i < nv; i++) {
            float send = up ? p[i] : p[i + nv];
            float recv = __shfl_xor_sync(FULL, send, off);
            float keep = up ? p[i + nv] : p[i];
            p[i] = keep + recv;
        }
    }

    // hs[hl] = relu(mean_hl + b1) + relu(max_hl + b1), in-lane
    float hs = fmaxf(p[0] + b1v, 0.f) + fmaxf(p[1] + b1v, 0.f);

    // ---- layer 2: a[c] = 2*b2[c] + sum_j hs[j]*W2[j][c] ----
    float4 a = make_float4(2.f*b2v.x, 2.f*b2v.y, 2.f*b2v.z, 2.f*b2v.w);
    #pragma unroll
    for (int j = 0; j < HID; j++) {
        float  hj = __shfl_sync(FULL, hs, (lane & 16) | j);
        float4 w  = sW2p[j * 16 + hl];
        a.x += hj*w.x; a.y += hj*w.y; a.z += hj*w.z; a.w += hj*w.w;
    }

    float4 xv = __ldg((const float4*)(xF + (size_t)n * C + 4 * hl));
    float4 o;
    o.x = xv.x / (1.f + expf(-a.x));
    o.y = xv.y / (1.f + expf(-a.y));
    o.z = xv.z / (1.f + expf(-a.z));
    o.w = xv.w / (1.f + expf(-a.w));
    *(float4*)(g_outse + (size_t)n * C + 4 * hl) = o;

    // ---- rowsum/rowmax of outse (16-lane reduction per half) ----
    float s  = o.x + o.y + o.z + o.w;
    float mm = fmaxf(fmaxf(o.x, o.y), fmaxf(o.z, o.w));
    #pragma unroll
    for (int off = 8; off >= 1; off >>= 1) {
        s  += __shfl_xor_sync(FULL, s, off);
        mm  = fmaxf(mm, __shfl_xor_sync(FULL, mm, off));
    }
    if (hl == 0)
        *(float2*)(g_rowstat + 2 * (size_t)n) = make_float2(s, mm);
}

// ---------------------------------------------------------------------------
// Kernel 2: z = (mean over k*c, max over k*c) of outse[idx], factored through
//           per-point rowstats. thread-per-point, 16 x 8B gathers.
// ---------------------------------------------------------------------------
__global__ __launch_bounds__(256) void k2_z(const int* __restrict__ idx, int N)
{
    int n = blockIdx.x * blockDim.x + threadIdx.x;
    if (n >= N) return;
    const int4* ib = (const int4*)(idx + (size_t)n * KNN);
    int4 q0 = __ldg(ib + 0), q1 = __ldg(ib + 1),
         q2 = __ldg(ib + 2), q3 = __ldg(ib + 3);
    const int nb[KNN] = { q0.x, q0.y, q0.z, q0.w,  q1.x, q1.y, q1.z, q1.w,
                          q2.x, q2.y, q2.z, q2.w,  q3.x, q3.y, q3.z, q3.w };
    float s = 0.f, mx = -INFINITY;
    #pragma unroll
    for (int k = 0; k < KNN; k++) {
        float2 rs = __ldg((const float2*)(g_rowstat + 2 * (size_t)nb[k]));
        s += rs.x;
        mx = fmaxf(mx, rs.y);
    }
    *(float2*)(g_z + 2 * (size_t)n) = make_float2(s * (1.f / (KNN * C)), mx);
}

// ---------------------------------------------------------------------------
// Kernel 3: sparse conv3d(2->1) over 27 voxel neighbors + final gating.
//           warp-per-point: lanes 0..26 each handle one conv tap.
// ---------------------------------------------------------------------------
__global__ __launch_bounds__(256) void k3_out(
    const float* __restrict__ conv_w,   // (27, 2, 1)
    const int*   __restrict__ conv_idx, // (N, 27)
    float*       __restrict__ out,
    int N)
{
    const int n    = (blockIdx.x * blockDim.x + threadIdx.x) >> 5;
    const int lane = threadIdx.x & 31;
    if (n >= N) return;

    float f = 0.f;
    if (lane < 27) {
        int m = __ldg(conv_idx + (size_t)n * 27 + lane);
        if (m >= 0) {
            float2 zz = __ldg((const float2*)(g_z + 2 * (size_t)m));
            float2 cw = __ldg((const float2*)(conv_w + 2 * lane));
            f = zz.x * cw.x + zz.y * cw.y;
        }
    }
    #pragma unroll
    for (int off = 16; off >= 1; off >>= 1)
        f += __shfl_xor_sync(FULL, f, off);

    float sg = 1.f / (1.f + expf(-f));
    float2 o = *(const float2*)(g_outse + (size_t)n * C + 2 * lane);
    *(float2*)(out + (size_t)n * C + 2 * lane) = make_float2(o.x * sg, o.y * sg);
}

// ---------------------------------------------------------------------------
// Launch: inputs in metadata order:
//   0 x_F (N*C f32), 1 W1 (C*HID), 2 b1 (HID), 3 W2 (HID*C), 4 b2 (C),
//   5 conv_w (27*2), 6 idx (N*KNN i32), 7 conv_idx (N*27 i32)
// ---------------------------------------------------------------------------
extern "C" void kernel_launch(void* const* d_in, const int* in_sizes, int n_in,
                              void* d_out, int out_size)
{
    const float* xF  = (const float*)d_in[0];
    const float* W1  = (const float*)d_in[1];
    const float* b1  = (const float*)d_in[2];
    const float* W2  = (const float*)d_in[3];
    const float* b2  = (const float*)d_in[4];
    const float* cw  = (const float*)d_in[5];
    const int*   idx = (const int*)d_in[6];
    const int*   cid = (const int*)d_in[7];
    float*       out = (float*)d_out;

    const int N = in_sizes[0] / C;                 // 100000

    const int npairs     = (N + 1) / 2;            // 2 points per warp
    const int k1_blocks  = (npairs + 7) / 8;       // 8 warps per block
    k1_gate<<<k1_blocks, 256>>>(xF, W1, b1, W2, b2, idx, N);
    k2_z  <<<(N + 255) / 256, 256>>>(idx, N);
    k3_out<<<(N * 32 + 255) / 256, 256>>>(cw, cid, out, N);
}